// round 15
// baseline (speedup 1.0000x reference)
#include <cuda_runtime.h>
#include <cuda_fp16.h>
#include <cstdint>

#define C 128
#define PE_DIM 8
#define NG 512
#define MAXN 131072
#define MAXE 2000000
#define BN_EPS 1e-5f
#define SB 1024
#define WLD 136          // smem leading dim in halves (pad: conflict-free ldmatrix)

// ---------------- scratch (device globals) ----------------
__device__ float   g_h[(size_t)MAXN * C];
__device__ __half2 g_hh[(size_t)MAXN * (C / 2)];   // fp16 shadow, PRESCALED by dinv[n]
__device__ __half  g_aggh[(size_t)MAXN * C];       // fp16 aggregated features (GEMM A)
__device__ __half  g_linh[(size_t)MAXN * C];       // fp16 GEMM output
__device__ int     g_degi[MAXN];
__device__ int     g_cur[MAXN];
__device__ int     g_incl[MAXN];
__device__ int     g_bsum[1024];
__device__ int     g_off[MAXN + 1];
__device__ float   g_dinv[MAXN];
__device__ int     g_csr[MAXE];                    // col index only (norm separable)
__device__ double  g_stats[3 * 256];               // per layer: [0..127]=sum [128..255]=sumsq
__device__ float   g_pool[NG * C];
__device__ float   g_cnt[NG];
__device__ int     g_e64, g_b64;

// ---------------- helpers ----------------
__device__ __forceinline__ int ldidx(const void* p, long long i, int is64) {
    if (is64) return (int)((const long long*)p)[i];
    return ((const int*)p)[i];
}

__device__ __forceinline__ void red4(float* p, float a, float b, float c, float d) {
    asm volatile("red.global.add.v4.f32 [%0], {%1,%2,%3,%4};"
                 :: "l"(p), "f"(a), "f"(b), "f"(c), "f"(d) : "memory");
}

__device__ __forceinline__ void ldsm_x4(uint32_t& r0, uint32_t& r1, uint32_t& r2, uint32_t& r3,
                                        uint32_t addr) {
    asm volatile("ldmatrix.sync.aligned.m8n8.x4.shared.b16 {%0,%1,%2,%3}, [%4];"
                 : "=r"(r0), "=r"(r1), "=r"(r2), "=r"(r3) : "r"(addr));
}

__device__ __forceinline__ void ldsm_x4t(uint32_t& r0, uint32_t& r1, uint32_t& r2, uint32_t& r3,
                                         uint32_t addr) {
    asm volatile("ldmatrix.sync.aligned.m8n8.x4.trans.shared.b16 {%0,%1,%2,%3}, [%4];"
                 : "=r"(r0), "=r"(r1), "=r"(r2), "=r"(r3) : "r"(addr));
}

__device__ __forceinline__ void mma16816(float* c, const uint32_t* a, const uint32_t* b) {
    asm volatile("mma.sync.aligned.m16n8k16.row.col.f32.f16.f16.f32 "
                 "{%0,%1,%2,%3},{%4,%5,%6,%7},{%8,%9},{%0,%1,%2,%3};"
                 : "+f"(c[0]), "+f"(c[1]), "+f"(c[2]), "+f"(c[3])
                 : "r"(a[0]), "r"(a[1]), "r"(a[2]), "r"(a[3]), "r"(b[0]), "r"(b[1]));
}

// ---------------- init + dtype detection (blocks 0/1 sample the index bufs) ---
__global__ void k_init(int N, const void* pe_, long long ne, const void* pb_, long long nbm) {
    if (blockIdx.x < 2) {
        __shared__ int ok;
        if (threadIdx.x == 0) ok = 1;
        __syncthreads();
        const void* p = (blockIdx.x == 0) ? pe_ : pb_;
        long long elems = (blockIdx.x == 0) ? ne : nbm;
        long long half = elems / 2;
        if (half > 0) {
            const unsigned long long* q = (const unsigned long long*)p;
            long long pos = (long long)threadIdx.x * (half - 1) / 255;
            if (pos >= half) pos = half - 1;
            if (q[pos] >> 32) ok = 0;
        }
        __syncthreads();
        if (threadIdx.x == 0) { if (blockIdx.x == 0) g_e64 = ok; else g_b64 = ok; }
    }
    int i = blockIdx.x * blockDim.x + threadIdx.x;
    if (i < N) { g_degi[i] = 0; g_cur[i] = 0; }
    if (i < NG * C) g_pool[i] = 0.0f;
    if (i < NG) g_cnt[i] = 0.0f;
    if (i < 3 * 256) g_stats[i] = 0.0;
}

// ---------------- CSR build (ordered segments via prefix scan) ----------------
__global__ void k_deg(const void* eix, int E) {
    int e = blockIdx.x * blockDim.x + threadIdx.x;
    if (e >= E) return;
    atomicAdd(&g_degi[ldidx(eix, e, g_e64)], 1);
}

__global__ void k_scan1(int N) {
    __shared__ int sm[SB];
    int i = blockIdx.x * SB + threadIdx.x;
    int v = (i < N) ? g_degi[i] : 0;
    if (i < N) g_dinv[i] = (v > 0) ? rsqrtf((float)v) : 0.0f;   // fused dinv
    sm[threadIdx.x] = v; __syncthreads();
    for (int o = 1; o < SB; o <<= 1) {
        int t = (threadIdx.x >= o) ? sm[threadIdx.x - o] : 0;
        __syncthreads();
        sm[threadIdx.x] += t;
        __syncthreads();
    }
    if (i < N) g_incl[i] = sm[threadIdx.x];
    if (threadIdx.x == SB - 1) g_bsum[blockIdx.x] = sm[SB - 1];
}

__global__ void k_scan2(int nb) {
    __shared__ int sm[1024];
    int v = (threadIdx.x < nb) ? g_bsum[threadIdx.x] : 0;
    sm[threadIdx.x] = v; __syncthreads();
    for (int o = 1; o < 1024; o <<= 1) {
        int t = (threadIdx.x >= o) ? sm[threadIdx.x - o] : 0;
        __syncthreads();
        sm[threadIdx.x] += t;
        __syncthreads();
    }
    if (threadIdx.x < nb) g_bsum[threadIdx.x] = sm[threadIdx.x] - v;   // exclusive
}

__global__ void k_scan3(int N) {
    int i = blockIdx.x * blockDim.x + threadIdx.x;
    if (i == 0) g_off[0] = 0;
    if (i < N) g_off[i + 1] = g_incl[i] + g_bsum[i >> 10];
}

// fill: col index only — no dinv gathers (norm is separable, folded into shadow)
__global__ void k_fill(const void* eix, int E) {
    int e = blockIdx.x * blockDim.x + threadIdx.x;
    if (e >= E) return;
    int is64 = g_e64;
    int r = ldidx(eix, e, is64);
    int c = ldidx(eix, (long long)E + e, is64);
    int pos = g_off[r] + atomicAdd(&g_cur[r], 1);
    g_csr[pos] = c;
}

// ---------------- input projection (fp32 h + prescaled fp16 shadow) -----------
__global__ void k_input(const float* __restrict__ x, const float* __restrict__ pe,
                        const float* __restrict__ nW, const float* __restrict__ nb,
                        const float* __restrict__ pW, const float* __restrict__ pb, int N) {
    int idx = blockIdx.x * blockDim.x + threadIdx.x;   // N*64, 2 channels each
    if (idx >= N * 64) return;
    int n = idx >> 6, c = (idx & 63) * 2;
    float xv = x[n];
    float v0 = xv * nW[c]     + nb[c]     + pb[c];
    float v1 = xv * nW[c + 1] + nb[c + 1] + pb[c + 1];
#pragma unroll
    for (int k = 0; k < PE_DIM; k++) {
        float p = pe[n * PE_DIM + k];
        v0 += p * pW[k * C + c];
        v1 += p * pW[k * C + c + 1];
    }
    ((float2*)g_h)[idx] = make_float2(v0, v1);
    float dv = g_dinv[n];
    g_hh[idx] = __floats2half2_rn(v0 * dv, v1 * dv);
}

// ---------------- aggregation v4: prescaled gather, pure adds -----------------
// agg[w] = h[w] + dinv[w] * sum(hh[col]);  hh already carries dinv[col]
__global__ void k_aggr(int N) {
    int w = (blockIdx.x * blockDim.x + threadIdx.x) >> 5;
    int lane = threadIdx.x & 31;
    if (w >= N) return;
    int grp = lane >> 4;          // edge slot 0/1
    int sub = lane & 15;          // channel chunk (8 halves = 16 B)
    int s = g_off[w], e = g_off[w + 1];
    const uint4* hb = (const uint4*)g_hh;     // row = 16 uint4
    float acc[8] = {0.f, 0.f, 0.f, 0.f, 0.f, 0.f, 0.f, 0.f};
    int i = s + grp;
    for (; i + 6 < e; i += 8) {               // four edges per group-iteration
        int ca = g_csr[i];
        int cb = g_csr[i + 2];
        int cc = g_csr[i + 4];
        int cd = g_csr[i + 6];
        uint4 va = hb[(size_t)ca * 16 + sub];
        uint4 vb = hb[(size_t)cb * 16 + sub];
        uint4 vc = hb[(size_t)cc * 16 + sub];
        uint4 vd = hb[(size_t)cd * 16 + sub];
        const __half2* ha2 = (const __half2*)&va;
        const __half2* hb2 = (const __half2*)&vb;
        const __half2* hc2 = (const __half2*)&vc;
        const __half2* hd2 = (const __half2*)&vd;
#pragma unroll
        for (int t = 0; t < 4; t++) {
            float2 fa = __half22float2(ha2[t]);
            float2 fb = __half22float2(hb2[t]);
            float2 fc = __half22float2(hc2[t]);
            float2 fd = __half22float2(hd2[t]);
            acc[2 * t]     += (fa.x + fb.x) + (fc.x + fd.x);
            acc[2 * t + 1] += (fa.y + fb.y) + (fc.y + fd.y);
        }
    }
    for (; i < e; i += 2) {
        int ca = g_csr[i];
        uint4 va = hb[(size_t)ca * 16 + sub];
        const __half2* ha2 = (const __half2*)&va;
#pragma unroll
        for (int t = 0; t < 4; t++) {
            float2 fa = __half22float2(ha2[t]);
            acc[2 * t]     += fa.x;
            acc[2 * t + 1] += fa.y;
        }
    }
    // combine the two edge slots
#pragma unroll
    for (int t = 0; t < 8; t++)
        acc[t] += __shfl_xor_sync(0xffffffffu, acc[t], 16);
    if (lane < 16) {
        int deg = g_degi[w];
        float dinv = g_dinv[w];
        float hres[8];
        if (deg > 0) {
            // residual reconstructed from prescaled shadow: h = hh * sqrt(deg)
            float sq = sqrtf((float)deg);
            uint4 hr = hb[(size_t)w * 16 + sub];
            const __half2* hr2 = (const __half2*)&hr;
#pragma unroll
            for (int t = 0; t < 4; t++) {
                float2 fr = __half22float2(hr2[t]);
                hres[2 * t]     = fr.x * sq;
                hres[2 * t + 1] = fr.y * sq;
            }
        } else {
            float4 h0 = ((const float4*)g_h)[(size_t)w * 32 + sub * 2];
            float4 h1 = ((const float4*)g_h)[(size_t)w * 32 + sub * 2 + 1];
            hres[0] = h0.x; hres[1] = h0.y; hres[2] = h0.z; hres[3] = h0.w;
            hres[4] = h1.x; hres[5] = h1.y; hres[6] = h1.z; hres[7] = h1.w;
        }
        uint4 o;
        __half2* oh = (__half2*)&o;
#pragma unroll
        for (int t = 0; t < 4; t++)
            oh[t] = __floats2half2_rn(hres[2 * t]     + dinv * acc[2 * t],
                                      hres[2 * t + 1] + dinv * acc[2 * t + 1]);
        ((uint4*)g_aggh)[(size_t)w * 16 + sub] = o;
    }
}

// ---------------- tensor-core GEMM + fused BN stats (fp16 output) -------------
// block: 256 threads = 8 warps (4 M x 2 N); tile 128x128, K=128
__global__ void k_gemm(const float* __restrict__ Wg, int N, int layer) {
    extern __shared__ __half smh[];
    __half* Ws = smh;                 // [128][WLD]
    __half* As = smh + 128 * WLD;     // [128][WLD]
    __shared__ float sstat[256];
    int tid = threadIdx.x;
    int warp = tid >> 5, lane = tid & 31;
    int wm = warp & 3, wn = warp >> 2;

    sstat[tid] = 0.0f;

    // W fp32 -> fp16 smem (once per block)
    for (int i = tid; i < 128 * 64; i += 256) {
        int k = i >> 6, n2 = i & 63;
        float2 w = ((const float2*)Wg)[(size_t)k * 64 + n2];
        ((__half2*)(Ws + k * WLD))[n2] = __floats2half2_rn(w.x, w.y);
    }

    uint32_t as_base = (uint32_t)__cvta_generic_to_shared(As);
    uint32_t ws_base = (uint32_t)__cvta_generic_to_shared(Ws);

    int a_row  = lane & 15;
    int a_koff = (lane >> 4) << 3;
    int b_grp  = lane >> 3;
    int b_krow = ((b_grp & 1) << 3) + (lane & 7);
    int b_noff = (b_grp >> 1) << 3;

    int ntiles = (N + 127) >> 7;
    for (int t = blockIdx.x; t < ntiles; t += gridDim.x) {
        int row0 = t << 7;
        __syncthreads();
        for (int i = tid; i < 128 * 16; i += 256) {
            int r = i >> 4, c4 = i & 15;
            uint4 v = make_uint4(0u, 0u, 0u, 0u);
            if (row0 + r < N) v = ((const uint4*)g_aggh)[(size_t)(row0 + r) * 16 + c4];
            *(uint4*)(As + r * WLD + c4 * 8) = v;
        }
        __syncthreads();

        float acc[2][8][4] = {};

#pragma unroll
        for (int ks = 0; ks < 8; ks++) {
            int kb = ks << 4;
            uint32_t a[2][4];
#pragma unroll
            for (int mi = 0; mi < 2; mi++) {
                int row = wm * 32 + mi * 16 + a_row;
                ldsm_x4(a[mi][0], a[mi][1], a[mi][2], a[mi][3],
                        as_base + (uint32_t)(row * WLD + kb + a_koff) * 2);
            }
#pragma unroll
            for (int np = 0; np < 4; np++) {
                uint32_t b0, b1, b2, b3;
                int ncol = wn * 64 + np * 16 + b_noff;
                ldsm_x4t(b0, b1, b2, b3,
                         ws_base + (uint32_t)((kb + b_krow) * WLD + ncol) * 2);
                uint32_t bA[2] = {b0, b1}, bB[2] = {b2, b3};
                mma16816(acc[0][2 * np],     a[0], bA);
                mma16816(acc[0][2 * np + 1], a[0], bB);
                mma16816(acc[1][2 * np],     a[1], bA);
                mma16816(acc[1][2 * np + 1], a[1], bB);
            }
        }

        // store output tile (fp16)
        int r_base = row0 + wm * 32 + (lane >> 2);
        int c_base = wn * 64 + (lane & 3) * 2;
#pragma unroll
        for (int mi = 0; mi < 2; mi++)
#pragma unroll
            for (int na = 0; na < 8; na++) {
                int r0 = r_base + mi * 16, c = c_base + na * 8;
                if (r0 < N)
                    *(__half2*)&g_linh[(size_t)r0 * C + c] =
                        __floats2half2_rn(acc[mi][na][0], acc[mi][na][1]);
                if (r0 + 8 < N)
                    *(__half2*)&g_linh[(size_t)(r0 + 8) * C + c] =
                        __floats2half2_rn(acc[mi][na][2], acc[mi][na][3]);
            }

        // fused BN stats from exact fp32 accumulators (padded rows = zeros)
#pragma unroll
        for (int na = 0; na < 8; na++)
#pragma unroll
            for (int j = 0; j < 2; j++) {
                float v0 = acc[0][na][j], v1 = acc[0][na][j + 2];
                float v2 = acc[1][na][j], v3 = acc[1][na][j + 2];
                float s = v0 + v1 + v2 + v3;
                float q = v0 * v0 + v1 * v1 + v2 * v2 + v3 * v3;
#pragma unroll
                for (int m = 4; m <= 16; m <<= 1) {
                    s += __shfl_xor_sync(0xffffffffu, s, m);
                    q += __shfl_xor_sync(0xffffffffu, q, m);
                }
                if ((lane >> 2) == 0) {
                    int c = wn * 64 + na * 8 + (lane & 3) * 2 + j;
                    atomicAdd(&sstat[c], s);
                    atomicAdd(&sstat[128 + c], q);
                }
            }
    }

    __syncthreads();
    if (tid < 128) {
        atomicAdd(&g_stats[layer * 256 + tid], (double)sstat[tid]);
        atomicAdd(&g_stats[layer * 256 + 128 + tid], (double)sstat[128 + tid]);
    }
}

// ---------------- BN apply + ReLU + residual (+ optional fused pool) ----------
__global__ void k_apply(const float* __restrict__ gamma, const float* __restrict__ beta,
                        int layer, int N, int fuse_pool, const void* batch) {
    __shared__ float sc[C], sh[C];
    if (threadIdx.x < C) {
        int cc = threadIdx.x;
        double mean = g_stats[layer * 256 + cc] / (double)N;
        double var  = g_stats[layer * 256 + 128 + cc] / (double)N - mean * mean;
        float inv = rsqrtf((float)var + BN_EPS);
        float s = gamma[cc] * inv;
        sc[cc] = s;
        sh[cc] = beta[cc] - (float)mean * s;
    }
    __syncthreads();
    int idx = blockIdx.x * blockDim.x + threadIdx.x;
    if (idx >= N * 32) return;
    int n = idx >> 5, j = idx & 31;
    int c = j * 4;
    uint2 lraw = ((const uint2*)g_linh)[idx];
    float2 l0 = __half22float2(*(__half2*)&lraw.x);
    float2 l1 = __half22float2(*(__half2*)&lraw.y);
    float4 hv = ((float4*)g_h)[idx];
    hv.x += fmaxf(l0.x * sc[c + 0] + sh[c + 0], 0.0f);
    hv.y += fmaxf(l0.y * sc[c + 1] + sh[c + 1], 0.0f);
    hv.z += fmaxf(l1.x * sc[c + 2] + sh[c + 2], 0.0f);
    hv.w += fmaxf(l1.y * sc[c + 3] + sh[c + 3], 0.0f);
    if (fuse_pool) {
        int g = ldidx(batch, n, g_b64);
        red4(&g_pool[g * C + c], hv.x, hv.y, hv.z, hv.w);
        if (j == 0) atomicAdd(&g_cnt[g], 1.0f);
    } else {
        ((float4*)g_h)[idx] = hv;
        float dv = g_dinv[n];
        uint2 hp;
        *(__half2*)&hp.x = __floats2half2_rn(hv.x * dv, hv.y * dv);
        *(__half2*)&hp.y = __floats2half2_rn(hv.z * dv, hv.w * dv);
        ((uint2*)g_hh)[idx] = hp;
    }
}

// ---------------- fused head: out[g] = relu(pool@W1+b1) @ W2 + b2 -------------
__global__ void k_head(const float* __restrict__ W1, const float* __restrict__ b1,
                       const float* __restrict__ W2, const float* __restrict__ b2,
                       float* __restrict__ out) {
    __shared__ float ps[C];
    __shared__ float red[4];
    int g = blockIdx.x, c = threadIdx.x;
    float cn = fmaxf(g_cnt[g], 1.0f);
    ps[c] = g_pool[g * C + c] / cn;
    __syncthreads();
    float acc = b1[c];
#pragma unroll 8
    for (int k = 0; k < C; k++) acc += ps[k] * W1[k * C + c];
    float v = fmaxf(acc, 0.0f) * W2[c];
#pragma unroll
    for (int o = 16; o; o >>= 1) v += __shfl_xor_sync(0xffffffffu, v, o);
    if ((c & 31) == 0) red[c >> 5] = v;
    __syncthreads();
    if (c == 0) out[g] = red[0] + red[1] + red[2] + red[3] + b2[0];
}

// ---------------- launch ----------------
extern "C" void kernel_launch(void* const* d_in, const int* in_sizes, int n_in,
                              void* d_out, int out_size) {
    int o = (n_in >= 17) ? 1 : 0;
    const float* x     = (const float*)d_in[0];
    const float* pe    = (const float*)d_in[1];
    const void*  eix   = d_in[2];
    const void*  batch = d_in[3];
    const float* nW    = (const float*)d_in[4 + o];
    const float* nb    = (const float*)d_in[5 + o];
    const float* pW    = (const float*)d_in[6 + o];
    const float* pb    = (const float*)d_in[7 + o];
    const float* convW = (const float*)d_in[8 + o];
    const float* gamma = (const float*)d_in[10 + o];
    const float* beta  = (const float*)d_in[11 + o];
    const float* W1    = (const float*)d_in[12 + o];
    const float* b1    = (const float*)d_in[13 + o];
    const float* W2    = (const float*)d_in[14 + o];
    const float* b2    = (const float*)d_in[15 + o];

    int N = in_sizes[0];
    int E = in_sizes[2] / 2;
    if (N > MAXN) N = MAXN;
    if (E > MAXE) E = MAXE;

    const int gsmem = 2 * 128 * WLD * (int)sizeof(__half);   // 69632 B dynamic
    cudaFuncSetAttribute(k_gemm, cudaFuncAttributeMaxDynamicSharedMemorySize, gsmem);

    int initN = (N > NG * C) ? N : NG * C;
    k_init<<<(initN + 255) / 256, 256>>>(N, eix, (long long)in_sizes[2],
                                         batch, (long long)in_sizes[3]);

    int nb2 = (N + SB - 1) / SB;
    k_deg<<<(E + 255) / 256, 256>>>(eix, E);
    k_scan1<<<nb2, SB>>>(N);
    k_scan2<<<1, 1024>>>(nb2);
    k_scan3<<<(N + 255) / 256, 256>>>(N);
    k_fill<<<(E + 255) / 256, 256>>>(eix, E);

    k_input<<<(N * 64 + 255) / 256, 256>>>(x, pe, nW, nb, pW, pb, N);

    int aggr_blocks = (N * 32 + 255) / 256;
    for (int l = 0; l < 3; l++) {
        k_aggr<<<aggr_blocks, 256>>>(N);
        k_gemm<<<296, 256, gsmem>>>(convW + (size_t)l * C * C, N, l);
        k_apply<<<(N * 32 + 255) / 256, 256>>>(gamma + l * C, beta + l * C,
                                               l, N, (l == 2) ? 1 : 0, batch);
    }

    k_head<<<NG, C>>>(W1, b1, W2, b2, (float*)d_out);
}

// round 16
// speedup vs baseline: 1.0351x; 1.0351x over previous
#include <cuda_runtime.h>
#include <cuda_fp16.h>
#include <cstdint>

#define C 128
#define PE_DIM 8
#define NG 512
#define MAXN 131072
#define MAXE 2000000
#define BN_EPS 1e-5f
#define SB 1024
#define WLD 136          // smem leading dim in halves (pad: conflict-free ldmatrix)

// ---------------- scratch (device globals) ----------------
__device__ float   g_h[(size_t)MAXN * C];
__device__ __half2 g_hh[(size_t)MAXN * (C / 2)];   // fp16 shadow of h (gather source)
__device__ __half  g_aggh[(size_t)MAXN * C];       // fp16 aggregated features (GEMM A)
__device__ __half  g_linh[(size_t)MAXN * C];       // fp16 GEMM output
__device__ int     g_degi[MAXN];
__device__ int     g_cur[MAXN];
__device__ int     g_incl[MAXN];
__device__ int     g_bsum[1024];
__device__ int     g_off[MAXN + 1];
__device__ float   g_dinv[MAXN];
__device__ int2    g_csr[MAXE];                    // (col, norm-bits)
__device__ double  g_stats[3 * 256];               // per layer: [0..127]=sum [128..255]=sumsq
__device__ float   g_pool[NG * C];
__device__ float   g_cnt[NG];
__device__ int     g_e64, g_b64;

// ---------------- helpers ----------------
__device__ __forceinline__ int ldidx(const void* p, long long i, int is64) {
    if (is64) return (int)((const long long*)p)[i];
    return ((const int*)p)[i];
}

__device__ __forceinline__ void red4(float* p, float a, float b, float c, float d) {
    asm volatile("red.global.add.v4.f32 [%0], {%1,%2,%3,%4};"
                 :: "l"(p), "f"(a), "f"(b), "f"(c), "f"(d) : "memory");
}

__device__ __forceinline__ void ldsm_x4(uint32_t& r0, uint32_t& r1, uint32_t& r2, uint32_t& r3,
                                        uint32_t addr) {
    asm volatile("ldmatrix.sync.aligned.m8n8.x4.shared.b16 {%0,%1,%2,%3}, [%4];"
                 : "=r"(r0), "=r"(r1), "=r"(r2), "=r"(r3) : "r"(addr));
}

__device__ __forceinline__ void ldsm_x4t(uint32_t& r0, uint32_t& r1, uint32_t& r2, uint32_t& r3,
                                         uint32_t addr) {
    asm volatile("ldmatrix.sync.aligned.m8n8.x4.trans.shared.b16 {%0,%1,%2,%3}, [%4];"
                 : "=r"(r0), "=r"(r1), "=r"(r2), "=r"(r3) : "r"(addr));
}

__device__ __forceinline__ void mma16816(float* c, const uint32_t* a, const uint32_t* b) {
    asm volatile("mma.sync.aligned.m16n8k16.row.col.f32.f16.f16.f32 "
                 "{%0,%1,%2,%3},{%4,%5,%6,%7},{%8,%9},{%0,%1,%2,%3};"
                 : "+f"(c[0]), "+f"(c[1]), "+f"(c[2]), "+f"(c[3])
                 : "r"(a[0]), "r"(a[1]), "r"(a[2]), "r"(a[3]), "r"(b[0]), "r"(b[1]));
}

// ---------------- init + dtype detection (blocks 0/1 sample the index bufs) ---
__global__ void k_init(int N, const void* pe_, long long ne, const void* pb_, long long nbm) {
    if (blockIdx.x < 2) {
        __shared__ int ok;
        if (threadIdx.x == 0) ok = 1;
        __syncthreads();
        const void* p = (blockIdx.x == 0) ? pe_ : pb_;
        long long elems = (blockIdx.x == 0) ? ne : nbm;
        long long half = elems / 2;
        if (half > 0) {
            const unsigned long long* q = (const unsigned long long*)p;
            long long pos = (long long)threadIdx.x * (half - 1) / 255;
            if (pos >= half) pos = half - 1;
            if (q[pos] >> 32) ok = 0;
        }
        __syncthreads();
        if (threadIdx.x == 0) { if (blockIdx.x == 0) g_e64 = ok; else g_b64 = ok; }
    }
    int i = blockIdx.x * blockDim.x + threadIdx.x;
    if (i < N) { g_degi[i] = 0; g_cur[i] = 0; }
    if (i < NG * C) g_pool[i] = 0.0f;
    if (i < NG) g_cnt[i] = 0.0f;
    if (i < 3 * 256) g_stats[i] = 0.0;
}

// ---------------- CSR build (ordered segments via prefix scan) ----------------
__global__ void k_deg(const void* eix, int E) {
    int e = blockIdx.x * blockDim.x + threadIdx.x;
    if (e >= E) return;
    atomicAdd(&g_degi[ldidx(eix, e, g_e64)], 1);
}

__global__ void k_scan1(int N) {
    __shared__ int sm[SB];
    int i = blockIdx.x * SB + threadIdx.x;
    int v = (i < N) ? g_degi[i] : 0;
    if (i < N) g_dinv[i] = (v > 0) ? rsqrtf((float)v) : 0.0f;   // fused dinv
    sm[threadIdx.x] = v; __syncthreads();
    for (int o = 1; o < SB; o <<= 1) {
        int t = (threadIdx.x >= o) ? sm[threadIdx.x - o] : 0;
        __syncthreads();
        sm[threadIdx.x] += t;
        __syncthreads();
    }
    if (i < N) g_incl[i] = sm[threadIdx.x];
    if (threadIdx.x == SB - 1) g_bsum[blockIdx.x] = sm[SB - 1];
}

__global__ void k_scan2(int nb) {
    __shared__ int sm[1024];
    int v = (threadIdx.x < nb) ? g_bsum[threadIdx.x] : 0;
    sm[threadIdx.x] = v; __syncthreads();
    for (int o = 1; o < 1024; o <<= 1) {
        int t = (threadIdx.x >= o) ? sm[threadIdx.x - o] : 0;
        __syncthreads();
        sm[threadIdx.x] += t;
        __syncthreads();
    }
    if (threadIdx.x < nb) g_bsum[threadIdx.x] = sm[threadIdx.x] - v;   // exclusive
}

__global__ void k_scan3(int N) {
    int i = blockIdx.x * blockDim.x + threadIdx.x;
    if (i == 0) g_off[0] = 0;
    if (i < N) g_off[i + 1] = g_incl[i] + g_bsum[i >> 10];
}

__global__ void k_fill(const void* eix, int E) {
    int e = blockIdx.x * blockDim.x + threadIdx.x;
    if (e >= E) return;
    int is64 = g_e64;
    int r = ldidx(eix, e, is64);
    int c = ldidx(eix, (long long)E + e, is64);
    int pos = g_off[r] + atomicAdd(&g_cur[r], 1);
    g_csr[pos] = make_int2(c, __float_as_int(g_dinv[r] * g_dinv[c]));
}

// ---------------- input projection (fp32 h + fp16 shadow) ---------------------
__global__ void k_input(const float* __restrict__ x, const float* __restrict__ pe,
                        const float* __restrict__ nW, const float* __restrict__ nb,
                        const float* __restrict__ pW, const float* __restrict__ pb, int N) {
    int idx = blockIdx.x * blockDim.x + threadIdx.x;   // N*64, 2 channels each
    if (idx >= N * 64) return;
    int n = idx >> 6, c = (idx & 63) * 2;
    float xv = x[n];
    float v0 = xv * nW[c]     + nb[c]     + pb[c];
    float v1 = xv * nW[c + 1] + nb[c + 1] + pb[c + 1];
#pragma unroll
    for (int k = 0; k < PE_DIM; k++) {
        float p = pe[n * PE_DIM + k];
        v0 += p * pW[k * C + c];
        v1 += p * pW[k * C + c + 1];
    }
    ((float2*)g_h)[idx] = make_float2(v0, v1);
    g_hh[idx] = __floats2half2_rn(v0, v1);
}

// ---------------- aggregation: warp/node, 4x unroll, __ldg NC gather ----------
// lanes 0-15 = edge slot 0, lanes 16-31 = edge slot 1; each lane covers 8 channels
__global__ void k_aggr(int N) {
    int w = (blockIdx.x * blockDim.x + threadIdx.x) >> 5;
    int lane = threadIdx.x & 31;
    if (w >= N) return;
    int grp = lane >> 4;          // edge slot 0/1
    int sub = lane & 15;          // channel chunk (8 halves = 16 B)
    int s = g_off[w], e = g_off[w + 1];
    const uint4* hb = (const uint4*)g_hh;     // row = 16 uint4
    float acc[8] = {0.f, 0.f, 0.f, 0.f, 0.f, 0.f, 0.f, 0.f};
    int i = s + grp;
    for (; i + 6 < e; i += 8) {               // four edges per group-iteration
        int2 ea = __ldg(&g_csr[i]);
        int2 eb = __ldg(&g_csr[i + 2]);
        int2 ec = __ldg(&g_csr[i + 4]);
        int2 ed = __ldg(&g_csr[i + 6]);
        uint4 va = __ldg(&hb[(size_t)ea.x * 16 + sub]);
        uint4 vb = __ldg(&hb[(size_t)eb.x * 16 + sub]);
        uint4 vc = __ldg(&hb[(size_t)ec.x * 16 + sub]);
        uint4 vd = __ldg(&hb[(size_t)ed.x * 16 + sub]);
        float na = __int_as_float(ea.y), nb2 = __int_as_float(eb.y);
        float nc = __int_as_float(ec.y), nd  = __int_as_float(ed.y);
        const __half2* ha2 = (const __half2*)&va;
        const __half2* hb2 = (const __half2*)&vb;
        const __half2* hc2 = (const __half2*)&vc;
        const __half2* hd2 = (const __half2*)&vd;
#pragma unroll
        for (int t = 0; t < 4; t++) {
            float2 fa = __half22float2(ha2[t]);
            float2 fb = __half22float2(hb2[t]);
            float2 fc = __half22float2(hc2[t]);
            float2 fd = __half22float2(hd2[t]);
            acc[2 * t]     += na * fa.x + nb2 * fb.x + nc * fc.x + nd * fd.x;
            acc[2 * t + 1] += na * fa.y + nb2 * fb.y + nc * fc.y + nd * fd.y;
        }
    }
    for (; i < e; i += 2) {
        int2 ea = __ldg(&g_csr[i]);
        float na = __int_as_float(ea.y);
        uint4 va = __ldg(&hb[(size_t)ea.x * 16 + sub]);
        const __half2* ha2 = (const __half2*)&va;
#pragma unroll
        for (int t = 0; t < 4; t++) {
            float2 fa = __half22float2(ha2[t]);
            acc[2 * t]     += na * fa.x;
            acc[2 * t + 1] += na * fa.y;
        }
    }
    // combine the two edge slots
#pragma unroll
    for (int t = 0; t < 8; t++)
        acc[t] += __shfl_xor_sync(0xffffffffu, acc[t], 16);
    if (lane < 16) {
        // residual from fp16 shadow: output is rounded to fp16 next anyway
        uint4 hr = __ldg(&hb[(size_t)w * 16 + sub]);
        const __half2* hr2 = (const __half2*)&hr;
#pragma unroll
        for (int t = 0; t < 4; t++) {
            float2 fr = __half22float2(hr2[t]);
            acc[2 * t]     += fr.x;
            acc[2 * t + 1] += fr.y;
        }
        uint4 o;
        __half2* oh = (__half2*)&o;
        oh[0] = __floats2half2_rn(acc[0], acc[1]);
        oh[1] = __floats2half2_rn(acc[2], acc[3]);
        oh[2] = __floats2half2_rn(acc[4], acc[5]);
        oh[3] = __floats2half2_rn(acc[6], acc[7]);
        ((uint4*)g_aggh)[(size_t)w * 16 + sub] = o;
    }
}

// ---------------- tensor-core GEMM + fused BN stats (fp16 output) -------------
// block: 256 threads = 8 warps (4 M x 2 N); tile 128x128, K=128
__global__ void k_gemm(const float* __restrict__ Wg, int N, int layer) {
    extern __shared__ __half smh[];
    __half* Ws = smh;                 // [128][WLD]
    __half* As = smh + 128 * WLD;     // [128][WLD]
    __shared__ float sstat[256];
    int tid = threadIdx.x;
    int warp = tid >> 5, lane = tid & 31;
    int wm = warp & 3, wn = warp >> 2;

    sstat[tid] = 0.0f;

    // W fp32 -> fp16 smem (once per block)
    for (int i = tid; i < 128 * 64; i += 256) {
        int k = i >> 6, n2 = i & 63;
        float2 w = ((const float2*)Wg)[(size_t)k * 64 + n2];
        ((__half2*)(Ws + k * WLD))[n2] = __floats2half2_rn(w.x, w.y);
    }

    uint32_t as_base = (uint32_t)__cvta_generic_to_shared(As);
    uint32_t ws_base = (uint32_t)__cvta_generic_to_shared(Ws);

    int a_row  = lane & 15;
    int a_koff = (lane >> 4) << 3;
    int b_grp  = lane >> 3;
    int b_krow = ((b_grp & 1) << 3) + (lane & 7);
    int b_noff = (b_grp >> 1) << 3;

    int ntiles = (N + 127) >> 7;
    for (int t = blockIdx.x; t < ntiles; t += gridDim.x) {
        int row0 = t << 7;
        __syncthreads();
        for (int i = tid; i < 128 * 16; i += 256) {
            int r = i >> 4, c4 = i & 15;
            uint4 v = make_uint4(0u, 0u, 0u, 0u);
            if (row0 + r < N) v = ((const uint4*)g_aggh)[(size_t)(row0 + r) * 16 + c4];
            *(uint4*)(As + r * WLD + c4 * 8) = v;
        }
        __syncthreads();

        float acc[2][8][4] = {};

#pragma unroll
        for (int ks = 0; ks < 8; ks++) {
            int kb = ks << 4;
            uint32_t a[2][4];
#pragma unroll
            for (int mi = 0; mi < 2; mi++) {
                int row = wm * 32 + mi * 16 + a_row;
                ldsm_x4(a[mi][0], a[mi][1], a[mi][2], a[mi][3],
                        as_base + (uint32_t)(row * WLD + kb + a_koff) * 2);
            }
#pragma unroll
            for (int np = 0; np < 4; np++) {
                uint32_t b0, b1, b2, b3;
                int ncol = wn * 64 + np * 16 + b_noff;
                ldsm_x4t(b0, b1, b2, b3,
                         ws_base + (uint32_t)((kb + b_krow) * WLD + ncol) * 2);
                uint32_t bA[2] = {b0, b1}, bB[2] = {b2, b3};
                mma16816(acc[0][2 * np],     a[0], bA);
                mma16816(acc[0][2 * np + 1], a[0], bB);
                mma16816(acc[1][2 * np],     a[1], bA);
                mma16816(acc[1][2 * np + 1], a[1], bB);
            }
        }

        // store output tile (fp16)
        int r_base = row0 + wm * 32 + (lane >> 2);
        int c_base = wn * 64 + (lane & 3) * 2;
#pragma unroll
        for (int mi = 0; mi < 2; mi++)
#pragma unroll
            for (int na = 0; na < 8; na++) {
                int r0 = r_base + mi * 16, c = c_base + na * 8;
                if (r0 < N)
                    *(__half2*)&g_linh[(size_t)r0 * C + c] =
                        __floats2half2_rn(acc[mi][na][0], acc[mi][na][1]);
                if (r0 + 8 < N)
                    *(__half2*)&g_linh[(size_t)(r0 + 8) * C + c] =
                        __floats2half2_rn(acc[mi][na][2], acc[mi][na][3]);
            }

        // fused BN stats from exact fp32 accumulators (padded rows = zeros)
#pragma unroll
        for (int na = 0; na < 8; na++)
#pragma unroll
            for (int j = 0; j < 2; j++) {
                float v0 = acc[0][na][j], v1 = acc[0][na][j + 2];
                float v2 = acc[1][na][j], v3 = acc[1][na][j + 2];
                float s = v0 + v1 + v2 + v3;
                float q = v0 * v0 + v1 * v1 + v2 * v2 + v3 * v3;
#pragma unroll
                for (int m = 4; m <= 16; m <<= 1) {
                    s += __shfl_xor_sync(0xffffffffu, s, m);
                    q += __shfl_xor_sync(0xffffffffu, q, m);
                }
                if ((lane >> 2) == 0) {
                    int c = wn * 64 + na * 8 + (lane & 3) * 2 + j;
                    atomicAdd(&sstat[c], s);
                    atomicAdd(&sstat[128 + c], q);
                }
            }
    }

    __syncthreads();
    if (tid < 128) {
        atomicAdd(&g_stats[layer * 256 + tid], (double)sstat[tid]);
        atomicAdd(&g_stats[layer * 256 + 128 + tid], (double)sstat[128 + tid]);
    }
}

// ---------------- BN apply + ReLU + residual (+ optional fused pool) ----------
__global__ void k_apply(const float* __restrict__ gamma, const float* __restrict__ beta,
                        int layer, int N, int fuse_pool, const void* batch) {
    __shared__ float sc[C], sh[C];
    if (threadIdx.x < C) {
        int cc = threadIdx.x;
        double mean = g_stats[layer * 256 + cc] / (double)N;
        double var  = g_stats[layer * 256 + 128 + cc] / (double)N - mean * mean;
        float inv = rsqrtf((float)var + BN_EPS);
        float s = gamma[cc] * inv;
        sc[cc] = s;
        sh[cc] = beta[cc] - (float)mean * s;
    }
    __syncthreads();
    int idx = blockIdx.x * blockDim.x + threadIdx.x;
    if (idx >= N * 32) return;
    int n = idx >> 5, j = idx & 31;
    int c = j * 4;
    uint2 lraw = ((const uint2*)g_linh)[idx];
    float2 l0 = __half22float2(*(__half2*)&lraw.x);
    float2 l1 = __half22float2(*(__half2*)&lraw.y);
    float4 hv = ((float4*)g_h)[idx];
    hv.x += fmaxf(l0.x * sc[c + 0] + sh[c + 0], 0.0f);
    hv.y += fmaxf(l0.y * sc[c + 1] + sh[c + 1], 0.0f);
    hv.z += fmaxf(l1.x * sc[c + 2] + sh[c + 2], 0.0f);
    hv.w += fmaxf(l1.y * sc[c + 3] + sh[c + 3], 0.0f);
    if (fuse_pool) {
        int g = ldidx(batch, n, g_b64);
        red4(&g_pool[g * C + c], hv.x, hv.y, hv.z, hv.w);
        if (j == 0) atomicAdd(&g_cnt[g], 1.0f);
    } else {
        ((float4*)g_h)[idx] = hv;
        uint2 hp;
        *(__half2*)&hp.x = __floats2half2_rn(hv.x, hv.y);
        *(__half2*)&hp.y = __floats2half2_rn(hv.z, hv.w);
        ((uint2*)g_hh)[idx] = hp;
    }
}

// ---------------- fused head: out[g] = relu(pool@W1+b1) @ W2 + b2 -------------
__global__ void k_head(const float* __restrict__ W1, const float* __restrict__ b1,
                       const float* __restrict__ W2, const float* __restrict__ b2,
                       float* __restrict__ out) {
    __shared__ float ps[C];
    __shared__ float red[4];
    int g = blockIdx.x, c = threadIdx.x;
    float cn = fmaxf(g_cnt[g], 1.0f);
    ps[c] = g_pool[g * C + c] / cn;
    __syncthreads();
    float acc = b1[c];
#pragma unroll 8
    for (int k = 0; k < C; k++) acc += ps[k] * W1[k * C + c];
    float v = fmaxf(acc, 0.0f) * W2[c];
#pragma unroll
    for (int o = 16; o; o >>= 1) v += __shfl_xor_sync(0xffffffffu, v, o);
    if ((c & 31) == 0) red[c >> 5] = v;
    __syncthreads();
    if (c == 0) out[g] = red[0] + red[1] + red[2] + red[3] + b2[0];
}

// ---------------- launch ----------------
extern "C" void kernel_launch(void* const* d_in, const int* in_sizes, int n_in,
                              void* d_out, int out_size) {
    int o = (n_in >= 17) ? 1 : 0;
    const float* x     = (const float*)d_in[0];
    const float* pe    = (const float*)d_in[1];
    const void*  eix   = d_in[2];
    const void*  batch = d_in[3];
    const float* nW    = (const float*)d_in[4 + o];
    const float* nb    = (const float*)d_in[5 + o];
    const float* pW    = (const float*)d_in[6 + o];
    const float* pb    = (const float*)d_in[7 + o];
    const float* convW = (const float*)d_in[8 + o];
    const float* gamma = (const float*)d_in[10 + o];
    const float* beta  = (const float*)d_in[11 + o];
    const float* W1    = (const float*)d_in[12 + o];
    const float* b1    = (const float*)d_in[13 + o];
    const float* W2    = (const float*)d_in[14 + o];
    const float* b2    = (const float*)d_in[15 + o];

    int N = in_sizes[0];
    int E = in_sizes[2] / 2;
    if (N > MAXN) N = MAXN;
    if (E > MAXE) E = MAXE;

    const int gsmem = 2 * 128 * WLD * (int)sizeof(__half);   // 69632 B dynamic
    cudaFuncSetAttribute(k_gemm, cudaFuncAttributeMaxDynamicSharedMemorySize, gsmem);

    int initN = (N > NG * C) ? N : NG * C;
    k_init<<<(initN + 255) / 256, 256>>>(N, eix, (long long)in_sizes[2],
                                         batch, (long long)in_sizes[3]);

    int nb2 = (N + SB - 1) / SB;
    k_deg<<<(E + 255) / 256, 256>>>(eix, E);
    k_scan1<<<nb2, SB>>>(N);
    k_scan2<<<1, 1024>>>(nb2);
    k_scan3<<<(N + 255) / 256, 256>>>(N);
    k_fill<<<(E + 255) / 256, 256>>>(eix, E);

    k_input<<<(N * 64 + 255) / 256, 256>>>(x, pe, nW, nb, pW, pb, N);

    int aggr_blocks = (N * 32 + 255) / 256;
    for (int l = 0; l < 3; l++) {
        k_aggr<<<aggr_blocks, 256>>>(N);
        k_gemm<<<296, 256, gsmem>>>(convW + (size_t)l * C * C, N, l);
        k_apply<<<(N * 32 + 255) / 256, 256>>>(gamma + l * C, beta + l * C,
                                               l, N, (l == 2) ? 1 : 0, batch);
    }

    k_head<<<NG, C>>>(W1, b1, W2, b2, (float*)d_out);
}

// round 17
// speedup vs baseline: 1.1273x; 1.0891x over previous
#include <cuda_runtime.h>
#include <cuda_fp16.h>
#include <cstdint>

#define C 128
#define PE_DIM 8
#define NG 512
#define MAXN 131072
#define MAXE 2000000
#define BN_EPS 1e-5f
#define SB 1024
#define WLD 136          // smem leading dim in halves (pad: conflict-free ldmatrix)

// ---------------- scratch (device globals) ----------------
__device__ __half2 g_hh[(size_t)MAXN * (C / 2)];   // h lives here (fp16 only)
__device__ __half  g_aggh[(size_t)MAXN * C];       // fp16 aggregated features (GEMM A)
__device__ __half  g_linh[(size_t)MAXN * C];       // fp16 GEMM output
__device__ int     g_degi[MAXN];
__device__ int     g_rank[MAXE];                   // per-edge rank within its segment
__device__ int     g_incl[MAXN];
__device__ int     g_bsum[1024];
__device__ int     g_off[MAXN + 1];
__device__ float   g_dinv[MAXN];
__device__ int2    g_csr[MAXE];                    // (col, norm-bits)
__device__ double  g_stats[3 * 256];               // per layer: [0..127]=sum [128..255]=sumsq
__device__ float   g_pool[NG * C];
__device__ float   g_cnt[NG];
__device__ int     g_e64, g_b64;

// ---------------- helpers ----------------
__device__ __forceinline__ int ldidx(const void* p, long long i, int is64) {
    if (is64) return (int)((const long long*)p)[i];
    return ((const int*)p)[i];
}

__device__ __forceinline__ void red4(float* p, float a, float b, float c, float d) {
    asm volatile("red.global.add.v4.f32 [%0], {%1,%2,%3,%4};"
                 :: "l"(p), "f"(a), "f"(b), "f"(c), "f"(d) : "memory");
}

__device__ __forceinline__ void ldsm_x4(uint32_t& r0, uint32_t& r1, uint32_t& r2, uint32_t& r3,
                                        uint32_t addr) {
    asm volatile("ldmatrix.sync.aligned.m8n8.x4.shared.b16 {%0,%1,%2,%3}, [%4];"
                 : "=r"(r0), "=r"(r1), "=r"(r2), "=r"(r3) : "r"(addr));
}

__device__ __forceinline__ void ldsm_x4t(uint32_t& r0, uint32_t& r1, uint32_t& r2, uint32_t& r3,
                                         uint32_t addr) {
    asm volatile("ldmatrix.sync.aligned.m8n8.x4.trans.shared.b16 {%0,%1,%2,%3}, [%4];"
                 : "=r"(r0), "=r"(r1), "=r"(r2), "=r"(r3) : "r"(addr));
}

__device__ __forceinline__ void mma16816(float* c, const uint32_t* a, const uint32_t* b) {
    asm volatile("mma.sync.aligned.m16n8k16.row.col.f32.f16.f16.f32 "
                 "{%0,%1,%2,%3},{%4,%5,%6,%7},{%8,%9},{%0,%1,%2,%3};"
                 : "+f"(c[0]), "+f"(c[1]), "+f"(c[2]), "+f"(c[3])
                 : "r"(a[0]), "r"(a[1]), "r"(a[2]), "r"(a[3]), "r"(b[0]), "r"(b[1]));
}

// ---------------- init + dtype detection (blocks 0/1 sample the index bufs) ---
__global__ void k_init(int N, const void* pe_, long long ne, const void* pb_, long long nbm) {
    if (blockIdx.x < 2) {
        __shared__ int ok;
        if (threadIdx.x == 0) ok = 1;
        __syncthreads();
        const void* p = (blockIdx.x == 0) ? pe_ : pb_;
        long long elems = (blockIdx.x == 0) ? ne : nbm;
        long long half = elems / 2;
        if (half > 0) {
            const unsigned long long* q = (const unsigned long long*)p;
            long long pos = (long long)threadIdx.x * (half - 1) / 255;
            if (pos >= half) pos = half - 1;
            if (q[pos] >> 32) ok = 0;
        }
        __syncthreads();
        if (threadIdx.x == 0) { if (blockIdx.x == 0) g_e64 = ok; else g_b64 = ok; }
    }
    int i = blockIdx.x * blockDim.x + threadIdx.x;
    if (i < N) g_degi[i] = 0;
    if (i < NG * C) g_pool[i] = 0.0f;
    if (i < NG) g_cnt[i] = 0.0f;
    if (i < 3 * 256) g_stats[i] = 0.0;
}

// ---------------- CSR build (ordered segments via prefix scan) ----------------
// deg also captures each edge's rank within its node segment (atomic return value)
__global__ void k_deg(const void* eix, int E) {
    int e = blockIdx.x * blockDim.x + threadIdx.x;
    if (e >= E) return;
    g_rank[e] = atomicAdd(&g_degi[ldidx(eix, e, g_e64)], 1);
}

__global__ void k_scan1(int N) {
    __shared__ int sm[SB];
    int i = blockIdx.x * SB + threadIdx.x;
    int v = (i < N) ? g_degi[i] : 0;
    if (i < N) g_dinv[i] = (v > 0) ? rsqrtf((float)v) : 0.0f;   // fused dinv
    sm[threadIdx.x] = v; __syncthreads();
    for (int o = 1; o < SB; o <<= 1) {
        int t = (threadIdx.x >= o) ? sm[threadIdx.x - o] : 0;
        __syncthreads();
        sm[threadIdx.x] += t;
        __syncthreads();
    }
    if (i < N) g_incl[i] = sm[threadIdx.x];
    if (threadIdx.x == SB - 1) g_bsum[blockIdx.x] = sm[SB - 1];
}

__global__ void k_scan2(int nb) {
    __shared__ int sm[1024];
    int v = (threadIdx.x < nb) ? g_bsum[threadIdx.x] : 0;
    sm[threadIdx.x] = v; __syncthreads();
    for (int o = 1; o < 1024; o <<= 1) {
        int t = (threadIdx.x >= o) ? sm[threadIdx.x - o] : 0;
        __syncthreads();
        sm[threadIdx.x] += t;
        __syncthreads();
    }
    if (threadIdx.x < nb) g_bsum[threadIdx.x] = sm[threadIdx.x] - v;   // exclusive
}

__global__ void k_scan3(int N) {
    int i = blockIdx.x * blockDim.x + threadIdx.x;
    if (i == 0) g_off[0] = 0;
    if (i < N) g_off[i + 1] = g_incl[i] + g_bsum[i >> 10];
}

// fill: position = segment start + precomputed rank; NO atomics
__global__ void k_fill(const void* eix, int E) {
    int e = blockIdx.x * blockDim.x + threadIdx.x;
    if (e >= E) return;
    int is64 = g_e64;
    int r = ldidx(eix, e, is64);
    int c = ldidx(eix, (long long)E + e, is64);
    int pos = g_off[r] + g_rank[e];
    g_csr[pos] = make_int2(c, __float_as_int(g_dinv[r] * g_dinv[c]));
}

// ---------------- input projection (fp16 h only) ------------------------------
__global__ void k_input(const float* __restrict__ x, const float* __restrict__ pe,
                        const float* __restrict__ nW, const float* __restrict__ nb,
                        const float* __restrict__ pW, const float* __restrict__ pb, int N) {
    int idx = blockIdx.x * blockDim.x + threadIdx.x;   // N*64, 2 channels each
    if (idx >= N * 64) return;
    int n = idx >> 6, c = (idx & 63) * 2;
    float xv = x[n];
    float v0 = xv * nW[c]     + nb[c]     + pb[c];
    float v1 = xv * nW[c + 1] + nb[c + 1] + pb[c + 1];
#pragma unroll
    for (int k = 0; k < PE_DIM; k++) {
        float p = pe[n * PE_DIM + k];
        v0 += p * pW[k * C + c];
        v1 += p * pW[k * C + c + 1];
    }
    g_hh[idx] = __floats2half2_rn(v0, v1);
}

// ---------------- aggregation: warp/node, 4x unroll, __ldg NC gather ----------
// lanes 0-15 = edge slot 0, lanes 16-31 = edge slot 1; each lane covers 8 channels
__global__ void k_aggr(int N) {
    int w = (blockIdx.x * blockDim.x + threadIdx.x) >> 5;
    int lane = threadIdx.x & 31;
    if (w >= N) return;
    int grp = lane >> 4;          // edge slot 0/1
    int sub = lane & 15;          // channel chunk (8 halves = 16 B)
    int s = g_off[w], e = g_off[w + 1];
    const uint4* hb = (const uint4*)g_hh;     // row = 16 uint4
    float acc[8] = {0.f, 0.f, 0.f, 0.f, 0.f, 0.f, 0.f, 0.f};
    int i = s + grp;
    for (; i + 6 < e; i += 8) {               // four edges per group-iteration
        int2 ea = __ldg(&g_csr[i]);
        int2 eb = __ldg(&g_csr[i + 2]);
        int2 ec = __ldg(&g_csr[i + 4]);
        int2 ed = __ldg(&g_csr[i + 6]);
        uint4 va = __ldg(&hb[(size_t)ea.x * 16 + sub]);
        uint4 vb = __ldg(&hb[(size_t)eb.x * 16 + sub]);
        uint4 vc = __ldg(&hb[(size_t)ec.x * 16 + sub]);
        uint4 vd = __ldg(&hb[(size_t)ed.x * 16 + sub]);
        float na = __int_as_float(ea.y), nb2 = __int_as_float(eb.y);
        float nc = __int_as_float(ec.y), nd  = __int_as_float(ed.y);
        const __half2* ha2 = (const __half2*)&va;
        const __half2* hb2 = (const __half2*)&vb;
        const __half2* hc2 = (const __half2*)&vc;
        const __half2* hd2 = (const __half2*)&vd;
#pragma unroll
        for (int t = 0; t < 4; t++) {
            float2 fa = __half22float2(ha2[t]);
            float2 fb = __half22float2(hb2[t]);
            float2 fc = __half22float2(hc2[t]);
            float2 fd = __half22float2(hd2[t]);
            acc[2 * t]     += na * fa.x + nb2 * fb.x + nc * fc.x + nd * fd.x;
            acc[2 * t + 1] += na * fa.y + nb2 * fb.y + nc * fc.y + nd * fd.y;
        }
    }
    for (; i < e; i += 2) {
        int2 ea = __ldg(&g_csr[i]);
        float na = __int_as_float(ea.y);
        uint4 va = __ldg(&hb[(size_t)ea.x * 16 + sub]);
        const __half2* ha2 = (const __half2*)&va;
#pragma unroll
        for (int t = 0; t < 4; t++) {
            float2 fa = __half22float2(ha2[t]);
            acc[2 * t]     += na * fa.x;
            acc[2 * t + 1] += na * fa.y;
        }
    }
    // combine the two edge slots
#pragma unroll
    for (int t = 0; t < 8; t++)
        acc[t] += __shfl_xor_sync(0xffffffffu, acc[t], 16);
    if (lane < 16) {
        uint4 hr = __ldg(&hb[(size_t)w * 16 + sub]);
        const __half2* hr2 = (const __half2*)&hr;
#pragma unroll
        for (int t = 0; t < 4; t++) {
            float2 fr = __half22float2(hr2[t]);
            acc[2 * t]     += fr.x;
            acc[2 * t + 1] += fr.y;
        }
        uint4 o;
        __half2* oh = (__half2*)&o;
        oh[0] = __floats2half2_rn(acc[0], acc[1]);
        oh[1] = __floats2half2_rn(acc[2], acc[3]);
        oh[2] = __floats2half2_rn(acc[4], acc[5]);
        oh[3] = __floats2half2_rn(acc[6], acc[7]);
        ((uint4*)g_aggh)[(size_t)w * 16 + sub] = o;
    }
}

// ---------------- tensor-core GEMM + fused BN stats (fp16 output) -------------
// block: 256 threads = 8 warps (4 M x 2 N); tile 128x128, K=128
__global__ void k_gemm(const float* __restrict__ Wg, int N, int layer) {
    extern __shared__ __half smh[];
    __half* Ws = smh;                 // [128][WLD]
    __half* As = smh + 128 * WLD;     // [128][WLD]
    __shared__ float sstat[256];
    int tid = threadIdx.x;
    int warp = tid >> 5, lane = tid & 31;
    int wm = warp & 3, wn = warp >> 2;

    sstat[tid] = 0.0f;

    // W fp32 -> fp16 smem (once per block)
    for (int i = tid; i < 128 * 64; i += 256) {
        int k = i >> 6, n2 = i & 63;
        float2 w = ((const float2*)Wg)[(size_t)k * 64 + n2];
        ((__half2*)(Ws + k * WLD))[n2] = __floats2half2_rn(w.x, w.y);
    }

    uint32_t as_base = (uint32_t)__cvta_generic_to_shared(As);
    uint32_t ws_base = (uint32_t)__cvta_generic_to_shared(Ws);

    int a_row  = lane & 15;
    int a_koff = (lane >> 4) << 3;
    int b_grp  = lane >> 3;
    int b_krow = ((b_grp & 1) << 3) + (lane & 7);
    int b_noff = (b_grp >> 1) << 3;

    int ntiles = (N + 127) >> 7;
    for (int t = blockIdx.x; t < ntiles; t += gridDim.x) {
        int row0 = t << 7;
        __syncthreads();
        for (int i = tid; i < 128 * 16; i += 256) {
            int r = i >> 4, c4 = i & 15;
            uint4 v = make_uint4(0u, 0u, 0u, 0u);
            if (row0 + r < N) v = ((const uint4*)g_aggh)[(size_t)(row0 + r) * 16 + c4];
            *(uint4*)(As + r * WLD + c4 * 8) = v;
        }
        __syncthreads();

        float acc[2][8][4] = {};

#pragma unroll
        for (int ks = 0; ks < 8; ks++) {
            int kb = ks << 4;
            uint32_t a[2][4];
#pragma unroll
            for (int mi = 0; mi < 2; mi++) {
                int row = wm * 32 + mi * 16 + a_row;
                ldsm_x4(a[mi][0], a[mi][1], a[mi][2], a[mi][3],
                        as_base + (uint32_t)(row * WLD + kb + a_koff) * 2);
            }
#pragma unroll
            for (int np = 0; np < 4; np++) {
                uint32_t b0, b1, b2, b3;
                int ncol = wn * 64 + np * 16 + b_noff;
                ldsm_x4t(b0, b1, b2, b3,
                         ws_base + (uint32_t)((kb + b_krow) * WLD + ncol) * 2);
                uint32_t bA[2] = {b0, b1}, bB[2] = {b2, b3};
                mma16816(acc[0][2 * np],     a[0], bA);
                mma16816(acc[0][2 * np + 1], a[0], bB);
                mma16816(acc[1][2 * np],     a[1], bA);
                mma16816(acc[1][2 * np + 1], a[1], bB);
            }
        }

        // store output tile (fp16)
        int r_base = row0 + wm * 32 + (lane >> 2);
        int c_base = wn * 64 + (lane & 3) * 2;
#pragma unroll
        for (int mi = 0; mi < 2; mi++)
#pragma unroll
            for (int na = 0; na < 8; na++) {
                int r0 = r_base + mi * 16, c = c_base + na * 8;
                if (r0 < N)
                    *(__half2*)&g_linh[(size_t)r0 * C + c] =
                        __floats2half2_rn(acc[mi][na][0], acc[mi][na][1]);
                if (r0 + 8 < N)
                    *(__half2*)&g_linh[(size_t)(r0 + 8) * C + c] =
                        __floats2half2_rn(acc[mi][na][2], acc[mi][na][3]);
            }

        // fused BN stats from exact fp32 accumulators (padded rows = zeros)
#pragma unroll
        for (int na = 0; na < 8; na++)
#pragma unroll
            for (int j = 0; j < 2; j++) {
                float v0 = acc[0][na][j], v1 = acc[0][na][j + 2];
                float v2 = acc[1][na][j], v3 = acc[1][na][j + 2];
                float s = v0 + v1 + v2 + v3;
                float q = v0 * v0 + v1 * v1 + v2 * v2 + v3 * v3;
#pragma unroll
                for (int m = 4; m <= 16; m <<= 1) {
                    s += __shfl_xor_sync(0xffffffffu, s, m);
                    q += __shfl_xor_sync(0xffffffffu, q, m);
                }
                if ((lane >> 2) == 0) {
                    int c = wn * 64 + na * 8 + (lane & 3) * 2 + j;
                    atomicAdd(&sstat[c], s);
                    atomicAdd(&sstat[128 + c], q);
                }
            }
    }

    __syncthreads();
    if (tid < 128) {
        atomicAdd(&g_stats[layer * 256 + tid], (double)sstat[tid]);
        atomicAdd(&g_stats[layer * 256 + 128 + tid], (double)sstat[128 + tid]);
    }
}

// ---------------- BN apply + ReLU + residual (+ optional fused pool) ----------
// h is fp16-resident: h_new = hh + relu(bn(lin)), computed fp32, stored fp16
__global__ void k_apply(const float* __restrict__ gamma, const float* __restrict__ beta,
                        int layer, int N, int fuse_pool, const void* batch) {
    __shared__ float sc[C], sh[C];
    if (threadIdx.x < C) {
        int cc = threadIdx.x;
        double mean = g_stats[layer * 256 + cc] / (double)N;
        double var  = g_stats[layer * 256 + 128 + cc] / (double)N - mean * mean;
        float inv = rsqrtf((float)var + BN_EPS);
        float s = gamma[cc] * inv;
        sc[cc] = s;
        sh[cc] = beta[cc] - (float)mean * s;
    }
    __syncthreads();
    int idx = blockIdx.x * blockDim.x + threadIdx.x;
    if (idx >= N * 32) return;
    int n = idx >> 5, j = idx & 31;
    int c = j * 4;
    uint2 lraw = ((const uint2*)g_linh)[idx];
    float2 l0 = __half22float2(*(__half2*)&lraw.x);
    float2 l1 = __half22float2(*(__half2*)&lraw.y);
    uint2 hraw = ((const uint2*)g_hh)[idx];
    float2 h0 = __half22float2(*(__half2*)&hraw.x);
    float2 h1 = __half22float2(*(__half2*)&hraw.y);
    float hv0 = h0.x + fmaxf(l0.x * sc[c + 0] + sh[c + 0], 0.0f);
    float hv1 = h0.y + fmaxf(l0.y * sc[c + 1] + sh[c + 1], 0.0f);
    float hv2 = h1.x + fmaxf(l1.x * sc[c + 2] + sh[c + 2], 0.0f);
    float hv3 = h1.y + fmaxf(l1.y * sc[c + 3] + sh[c + 3], 0.0f);
    if (fuse_pool) {
        int g = ldidx(batch, n, g_b64);
        red4(&g_pool[g * C + c], hv0, hv1, hv2, hv3);
        if (j == 0) atomicAdd(&g_cnt[g], 1.0f);
    } else {
        uint2 hp;
        *(__half2*)&hp.x = __floats2half2_rn(hv0, hv1);
        *(__half2*)&hp.y = __floats2half2_rn(hv2, hv3);
        ((uint2*)g_hh)[idx] = hp;
    }
}

// ---------------- fused head: out[g] = relu(pool@W1+b1) @ W2 + b2 -------------
__global__ void k_head(const float* __restrict__ W1, const float* __restrict__ b1,
                       const float* __restrict__ W2, const float* __restrict__ b2,
                       float* __restrict__ out) {
    __shared__ float ps[C];
    __shared__ float red[4];
    int g = blockIdx.x, c = threadIdx.x;
    float cn = fmaxf(g_cnt[g], 1.0f);
    ps[c] = g_pool[g * C + c] / cn;
    __syncthreads();
    float acc = b1[c];
#pragma unroll 8
    for (int k = 0; k < C; k++) acc += ps[k] * W1[k * C + c];
    float v = fmaxf(acc, 0.0f) * W2[c];
#pragma unroll
    for (int o = 16; o; o >>= 1) v += __shfl_xor_sync(0xffffffffu, v, o);
    if ((c & 31) == 0) red[c >> 5] = v;
    __syncthreads();
    if (c == 0) out[g] = red[0] + red[1] + red[2] + red[3] + b2[0];
}

// ---------------- launch ----------------
extern "C" void kernel_launch(void* const* d_in, const int* in_sizes, int n_in,
                              void* d_out, int out_size) {
    int o = (n_in >= 17) ? 1 : 0;
    const float* x     = (const float*)d_in[0];
    const float* pe    = (const float*)d_in[1];
    const void*  eix   = d_in[2];
    const void*  batch = d_in[3];
    const float* nW    = (const float*)d_in[4 + o];
    const float* nb    = (const float*)d_in[5 + o];
    const float* pW    = (const float*)d_in[6 + o];
    const float* pb    = (const float*)d_in[7 + o];
    const float* convW = (const float*)d_in[8 + o];
    const float* gamma = (const float*)d_in[10 + o];
    const float* beta  = (const float*)d_in[11 + o];
    const float* W1    = (const float*)d_in[12 + o];
    const float* b1    = (const float*)d_in[13 + o];
    const float* W2    = (const float*)d_in[14 + o];
    const float* b2    = (const float*)d_in[15 + o];

    int N = in_sizes[0];
    int E = in_sizes[2] / 2;
    if (N > MAXN) N = MAXN;
    if (E > MAXE) E = MAXE;

    const int gsmem = 2 * 128 * WLD * (int)sizeof(__half);   // 69632 B dynamic
    cudaFuncSetAttribute(k_gemm, cudaFuncAttributeMaxDynamicSharedMemorySize, gsmem);

    int initN = (N > NG * C) ? N : NG * C;
    k_init<<<(initN + 255) / 256, 256>>>(N, eix, (long long)in_sizes[2],
                                         batch, (long long)in_sizes[3]);

    int nb2 = (N + SB - 1) / SB;
    k_deg<<<(E + 255) / 256, 256>>>(eix, E);
    k_scan1<<<nb2, SB>>>(N);
    k_scan2<<<1, 1024>>>(nb2);
    k_scan3<<<(N + 255) / 256, 256>>>(N);
    k_fill<<<(E + 255) / 256, 256>>>(eix, E);

    k_input<<<(N * 64 + 255) / 256, 256>>>(x, pe, nW, nb, pW, pb, N);

    int aggr_blocks = (N * 32 + 255) / 256;
    for (int l = 0; l < 3; l++) {
        k_aggr<<<aggr_blocks, 256>>>(N);
        k_gemm<<<296, 256, gsmem>>>(convW + (size_t)l * C * C, N, l);
        k_apply<<<(N * 32 + 255) / 256, 256>>>(gamma + l * C, beta + l * C,
                                               l, N, (l == 2) ? 1 : 0, batch);
    }

    k_head<<<NG, C>>>(W1, b1, W2, b2, (float*)d_out);
}